// round 10
// baseline (speedup 1.0000x reference)
#include <cuda_runtime.h>
#include <cuda_bf16.h>
#include <math.h>
#include <stdint.h>

constexpr int BATCH = 128, SEQT = 24, EMB = 512, HID = 1024, VOC = 12000;
constexpr int MALL = SEQT * BATCH;     // 3072, row m = t*128 + b
constexpr int G4 = 4 * HID;            // 4096
constexpr int VOCP = 12032;            // VOC padded to 128
constexpr int BK = 32;                 // K chunk
constexpr int LDT = 40;                // padded smem row stride (bf16)
constexpr int STAGES = 3;
constexpr int TA = 128 * LDT;          // 5120 elems: one 128-row tile
constexpr uint32_t SMEMSZ = STAGES * (4 * TA) * 2;      // 122880 B (big GEMMs)

// persistent recurrence smem plan:
//   [0, 163840)          W_hh resident: 32 k-chunks x (hi,lo) x [32 x 40] bf16
//   [163840, 204800)     A (h) stream: 2 stages x (hi,lo) x [128 x 40] bf16
//   [204800, 223232)     Cs staging [128][36] fp32
constexpr int LDB = 40;
constexpr int BT = 32 * LDB;                        // 1280 elems per W tile
constexpr uint32_t SMB_BYTES = 32 * 2 * BT * 2;     // 163840
constexpr uint32_t SMA_OFF   = SMB_BYTES;
constexpr uint32_t ASTAGE_B  = 2 * TA * 2;          // 20480 B per A stage
constexpr uint32_t CS_OFF    = SMA_OFF + 2 * ASTAGE_B;       // 204800
constexpr uint32_t SMEMSZ_P  = CS_OFF + 128 * 36 * 4;        // 223232

// ---------------- device scratch (allocation forbidden) ---------------------
__device__ __nv_bfloat16 g_xhi[(size_t)MALL * EMB],  g_xlo[(size_t)MALL * EMB];
__device__ __nv_bfloat16 g_wih_hi[(size_t)G4 * EMB], g_wih_lo[(size_t)G4 * EMB];
__device__ __nv_bfloat16 g_whh_hi[(size_t)G4 * HID], g_whh_lo[(size_t)G4 * HID]; // interleaved
__device__ __nv_bfloat16 g_wfc_hi[(size_t)VOCP * HID], g_wfc_lo[(size_t)VOCP * HID];
__device__ __nv_bfloat16 g_hhi[(size_t)MALL * HID],  g_hlo[(size_t)MALL * HID];
__device__ float g_gpre[(size_t)MALL * G4];
__device__ float g_cbuf[2 * BATCH * HID];
__device__ int   g_bar[SEQT];     // per-step barrier slots (zeroed by gather_split)

// ---------------- helpers ----------------------------------------------------
__device__ __forceinline__ uint32_t smem_u32(const void* p) {
    uint32_t a;
    asm("{ .reg .u64 t; cvta.to.shared.u64 t, %1; cvt.u32.u64 %0, t; }" : "=r"(a) : "l"(p));
    return a;
}
__device__ __forceinline__ void cp16(uint32_t d, const void* s) {
    asm volatile("cp.async.cg.shared.global [%0], [%1], 16;" :: "r"(d), "l"(s));
}
__device__ __forceinline__ void cp_commit() { asm volatile("cp.async.commit_group;"); }
template <int N> __device__ __forceinline__ void cp_wait() {
    asm volatile("cp.async.wait_group %0;" :: "n"(N));
}
__device__ __forceinline__ void ldsm4(uint32_t* r, uint32_t a) {
    asm volatile("ldmatrix.sync.aligned.m8n8.x4.shared.b16 {%0,%1,%2,%3}, [%4];"
                 : "=r"(r[0]), "=r"(r[1]), "=r"(r[2]), "=r"(r[3]) : "r"(a));
}
__device__ __forceinline__ void mma16816(float* d, const uint32_t* a, const uint32_t* b) {
    asm volatile("mma.sync.aligned.m16n8k16.row.col.f32.bf16.bf16.f32 "
                 "{%0,%1,%2,%3}, {%4,%5,%6,%7}, {%8,%9}, {%0,%1,%2,%3};"
                 : "+f"(d[0]), "+f"(d[1]), "+f"(d[2]), "+f"(d[3])
                 : "r"(a[0]), "r"(a[1]), "r"(a[2]), "r"(a[3]), "r"(b[0]), "r"(b[1]));
}
__device__ __forceinline__ void split1(float x, __nv_bfloat16& hi, __nv_bfloat16& lo) {
    hi = __float2bfloat16(x);
    lo = __float2bfloat16(x - __bfloat162float(hi));
}
__device__ __forceinline__ uint32_t pack2(__nv_bfloat16 a, __nv_bfloat16 b) {
    __nv_bfloat162 p = __halves2bfloat162(a, b);
    return *reinterpret_cast<uint32_t*>(&p);
}
__device__ __forceinline__ void split4(float4 v, uint2& hi, uint2& lo) {
    __nv_bfloat16 h0, l0, h1, l1, h2, l2, h3, l3;
    split1(v.x, h0, l0); split1(v.y, h1, l1);
    split1(v.z, h2, l2); split1(v.w, h3, l3);
    hi = make_uint2(pack2(h0, h1), pack2(h2, h3));
    lo = make_uint2(pack2(l0, l1), pack2(l2, l3));
}

// ---------------- preprocessing (vectorized) ----------------------------------
__global__ void split_plain4(const float* __restrict__ s, __nv_bfloat16* __restrict__ hi,
                             __nv_bfloat16* __restrict__ lo, int n4) {
    for (int i = blockIdx.x * blockDim.x + threadIdx.x; i < n4; i += gridDim.x * blockDim.x) {
        uint2 uh, ul;
        split4(reinterpret_cast<const float4*>(s)[i], uh, ul);
        reinterpret_cast<uint2*>(hi)[i] = uh;
        reinterpret_cast<uint2*>(lo)[i] = ul;
    }
}
// W_hh interleave: dst row d -> blk=d>>5, gate=(d>>3)&3, j=d&7 ;
// src row = gate*HID + blk*8 + j   (CTA blk owns hidden [blk*8, blk*8+8) x 4 gates)
__global__ void split_whh4(const float* __restrict__ s) {
    constexpr int N4 = G4 * HID / 4;
    for (int i = blockIdx.x * blockDim.x + threadIdx.x; i < N4; i += gridDim.x * blockDim.x) {
        const int d = i >> 8, k4 = i & 255;
        const int src = ((d >> 3) & 3) * HID + (d >> 5) * 8 + (d & 7);
        uint2 uh, ul;
        split4(*reinterpret_cast<const float4*>(s + (size_t)src * HID + k4 * 4), uh, ul);
        reinterpret_cast<uint2*>(g_whh_hi)[i] = uh;
        reinterpret_cast<uint2*>(g_whh_lo)[i] = ul;
    }
}
__global__ void split_wfc4(const float* __restrict__ s) {
    constexpr int N4 = VOCP * HID / 4;
    for (int i = blockIdx.x * blockDim.x + threadIdx.x; i < N4; i += gridDim.x * blockDim.x) {
        const int r = i >> 8;
        float4 v = (r < VOC) ? reinterpret_cast<const float4*>(s)[i]
                             : make_float4(0.f, 0.f, 0.f, 0.f);
        uint2 uh, ul;
        split4(v, uh, ul);
        reinterpret_cast<uint2*>(g_wfc_hi)[i] = uh;
        reinterpret_cast<uint2*>(g_wfc_lo)[i] = ul;
    }
}
__global__ void gather_split(const float* __restrict__ enc, const int* __restrict__ caps,
                             const float* __restrict__ emb) {
    if (blockIdx.x == 0 && threadIdx.x < SEQT) g_bar[threadIdx.x] = 0;  // reset barriers
    const int m = blockIdx.x, t = m >> 7, b = m & 127;
    const float* src = (t == 0) ? enc + (size_t)b * EMB
                                : emb + (size_t)caps[b * SEQT + (t - 1)] * EMB;
    const float4 v = reinterpret_cast<const float4*>(src)[threadIdx.x];
    const int i = m * (EMB / 4) + threadIdx.x;
    uint2 uh, ul;
    split4(v, uh, ul);
    reinterpret_cast<uint2*>(g_xhi)[i] = uh;
    reinterpret_cast<uint2*>(g_xlo)[i] = ul;
}

// ---------------- big-GEMM mainloop (unchanged from round 9) -----------------
// acc += 3-term A[128xK] @ B[128xK]^T. 8 warps (2Mx4N), warp tile 64x32, 3-stage.
__device__ __forceinline__ void gemm_main(
    const __nv_bfloat16* __restrict__ Ahi, const __nv_bfloat16* __restrict__ Alo,
    const __nv_bfloat16* __restrict__ Bhi, const __nv_bfloat16* __restrict__ Blo,
    int m0, int n0, int K, uint32_t sm, float (&acc)[4][4][4]) {
    constexpr int STAGE = 4 * TA;
    const int tid = threadIdx.x, warp = tid >> 5, lane = tid & 31;
    const int wm = (warp & 1) * 64, wn = (warp >> 1) * 32;
    const int l8 = lane & 7, lt = lane >> 3;
    const int nk = K / BK;

    auto load_stage = [&](int stage, int k0) {
        const uint32_t sbase = sm + stage * STAGE * 2;
#pragma unroll
        for (int q = 0; q < 8; q++) {
            const int idx = q * 256 + tid;
            const int tile = idx >> 9, rem = idx & 511, r = rem >> 2, c = rem & 3;
            const uint32_t dst = sbase + (tile * TA + r * LDT + c * 8) * 2;
            const __nv_bfloat16* src =
                (tile == 0 ? Ahi : tile == 1 ? Alo : tile == 2 ? Bhi : Blo)
                + (size_t)((tile < 2 ? m0 : n0) + r) * K + k0 + c * 8;
            cp16(dst, src);
        }
        cp_commit();
    };

    load_stage(0, 0);
    load_stage(1, BK);

    for (int kc = 0; kc < nk; kc++) {
        if (kc == nk - 1) cp_wait<0>(); else cp_wait<1>();
        __syncthreads();
        if (kc + STAGES - 1 < nk)
            load_stage((kc + STAGES - 1) % STAGES, (kc + STAGES - 1) * BK);
        const uint32_t sb = sm + (kc % STAGES) * STAGE * 2;
#pragma unroll
        for (int h = 0; h < 2; h++) {
            const int kk = h * 16;
            uint32_t aHi[4][4], aLo[4][4], bHi[4][2], bLo[4][2];
#pragma unroll
            for (int mi = 0; mi < 4; mi++) {
                const uint32_t ra = sb +
                    ((wm + mi * 16 + l8 + (lt & 1) * 8) * LDT + kk + (lt >> 1) * 8) * 2;
                ldsm4(aHi[mi], ra);
                ldsm4(aLo[mi], ra + TA * 2);
            }
#pragma unroll
            for (int nj = 0; nj < 2; nj++) {
                const uint32_t rb = sb + 2 * TA * 2 +
                    ((wn + nj * 16 + l8 + (lt >> 1) * 8) * LDT + kk + (lt & 1) * 8) * 2;
                uint32_t t4[4];
                ldsm4(t4, rb);
                bHi[nj * 2][0] = t4[0]; bHi[nj * 2][1] = t4[1];
                bHi[nj * 2 + 1][0] = t4[2]; bHi[nj * 2 + 1][1] = t4[3];
                ldsm4(t4, rb + TA * 2);
                bLo[nj * 2][0] = t4[0]; bLo[nj * 2][1] = t4[1];
                bLo[nj * 2 + 1][0] = t4[2]; bLo[nj * 2 + 1][1] = t4[3];
            }
#pragma unroll
            for (int mi = 0; mi < 4; mi++)
#pragma unroll
                for (int ni = 0; ni < 4; ni++) {
                    mma16816(acc[mi][ni], aHi[mi], bHi[ni]);
                    mma16816(acc[mi][ni], aLo[mi], bHi[ni]);
                    mma16816(acc[mi][ni], aHi[mi], bLo[ni]);
                }
        }
    }
    __syncthreads();
}

// ---------------- generic GEMM: C = A @ B^T + bias ---------------------------
template <int MODE>
__global__ __launch_bounds__(256, 1)
void mma_gemm(const __nv_bfloat16* __restrict__ Ahi, const __nv_bfloat16* __restrict__ Alo,
              const __nv_bfloat16* __restrict__ Bhi, const __nv_bfloat16* __restrict__ Blo,
              const float* __restrict__ b1, const float* __restrict__ b2,
              float* __restrict__ C, int K, int N) {
    extern __shared__ char smraw[];
    float acc[4][4][4];
#pragma unroll
    for (int a = 0; a < 4; a++)
#pragma unroll
        for (int b = 0; b < 4; b++)
#pragma unroll
            for (int c = 0; c < 4; c++) acc[a][b][c] = 0.f;

    const int m0 = blockIdx.y * 128, n0 = blockIdx.x * 128;
    gemm_main(Ahi, Alo, Bhi, Blo, m0, n0, K, smem_u32(smraw), acc);

    const int lane = threadIdx.x & 31, warp = threadIdx.x >> 5;
    const int wm = (warp & 1) * 64, wn = (warp >> 1) * 32;
    const int g = lane >> 2, tg = lane & 3;
#pragma unroll
    for (int mi = 0; mi < 4; mi++)
#pragma unroll
        for (int half = 0; half < 2; half++) {
            const int m = m0 + wm + mi * 16 + g + half * 8;
            const size_t rowBase = (MODE == 0)
                ? (size_t)m * N
                : ((size_t)(m & 127) * SEQT + (size_t)(m >> 7)) * N;
#pragma unroll
            for (int ni = 0; ni < 4; ni++) {
                const int n = n0 + wn + ni * 8 + tg * 2;
                if (MODE == 1 && n >= N) continue;
                const float2 bb = *reinterpret_cast<const float2*>(b1 + n);
                float2 v;
                v.x = acc[mi][ni][half * 2 + 0] + bb.x;
                v.y = acc[mi][ni][half * 2 + 1] + bb.y;
                if (MODE == 0) {
                    const float2 b2v = *reinterpret_cast<const float2*>(b2 + n);
                    v.x += b2v.x; v.y += b2v.y;
                }
                *reinterpret_cast<float2*>(C + rowBase + n) = v;
            }
        }
}

// ---------------- persistent recurrence --------------------------------------
// 128 CTAs (1/SM, co-resident). W_hh slice resident in smem for all 24 steps.
// Per step: stream h[t-1] (2-stage cp.async), 3-term MMA, fused cell update,
// global arrive+spin barrier between steps.
__global__ __launch_bounds__(256, 1)
void lstm_persistent() {
    extern __shared__ char smraw[];
    const uint32_t sm = smem_u32(smraw);
    const int tid = threadIdx.x, blk = blockIdx.x;
    const int warp = tid >> 5, lane = tid & 31;
    const int wm = (warp & 3) * 32, wn = (warp >> 2) * 16;     // 4M x 2N warps
    const int l8 = lane & 7, lt = lane >> 3;
    float* Cs = reinterpret_cast<float*>(smraw + CS_OFF);

    // ---- load resident W tiles once: 32 chunks x (hi,lo) x [32 x 40] ----
    for (int idx = tid; idx < 8192; idx += 256) {
        const int g = idx & 3, r = (idx >> 2) & 31, tl = (idx >> 7) & 1, c = idx >> 8;
        const uint32_t dst = sm + c * (2 * BT * 2) + tl * (BT * 2) + (r * LDB + g * 8) * 2;
        const __nv_bfloat16* src = (tl ? g_whh_lo : g_whh_hi)
            + (size_t)(blk * 32 + r) * HID + c * 32 + g * 8;
        cp16(dst, src);
    }
    cp_commit();
    cp_wait<0>();
    __syncthreads();

#pragma unroll 1
    for (int t = 0; t < SEQT; t++) {
        if (t > 0) {
            const __nv_bfloat16* Ahi = g_hhi + (size_t)(t - 1) * BATCH * HID;
            const __nv_bfloat16* Alo = g_hlo + (size_t)(t - 1) * BATCH * HID;
            float acc[2][2][4] = {};

            auto loadA = [&](int st, int k0) {
#pragma unroll
                for (int q = 0; q < 4; q++) {
                    const int idx = q * 256 + tid;
                    const int hl = idx >> 9, rem = idx & 511, r = rem >> 2, g = rem & 3;
                    const uint32_t dst = sm + SMA_OFF + st * ASTAGE_B + hl * (TA * 2)
                                       + (r * LDT + g * 8) * 2;
                    const __nv_bfloat16* s = (hl ? Alo : Ahi) + (size_t)r * HID + k0 + g * 8;
                    cp16(dst, s);
                }
                cp_commit();
            };
            loadA(0, 0);

            for (int c = 0; c < 32; c++) {
                cp_wait<0>();
                __syncthreads();
                if (c + 1 < 32) loadA((c + 1) & 1, (c + 1) * BK);
                const uint32_t sa = sm + SMA_OFF + (c & 1) * ASTAGE_B;
                const uint32_t sbch = sm + c * (2 * BT * 2);
#pragma unroll
                for (int h = 0; h < 2; h++) {
                    const int kk = h * 16;
                    uint32_t aHi[2][4], aLo[2][4], bHi[2][2], bLo[2][2];
#pragma unroll
                    for (int mi = 0; mi < 2; mi++) {
                        const uint32_t ra = sa +
                            ((wm + mi * 16 + l8 + (lt & 1) * 8) * LDT + kk + (lt >> 1) * 8) * 2;
                        ldsm4(aHi[mi], ra);
                        ldsm4(aLo[mi], ra + TA * 2);
                    }
                    {
                        const uint32_t rb = sbch +
                            ((wn + l8 + (lt >> 1) * 8) * LDB + kk + (lt & 1) * 8) * 2;
                        uint32_t t4[4];
                        ldsm4(t4, rb);
                        bHi[0][0] = t4[0]; bHi[0][1] = t4[1];
                        bHi[1][0] = t4[2]; bHi[1][1] = t4[3];
                        ldsm4(t4, rb + BT * 2);
                        bLo[0][0] = t4[0]; bLo[0][1] = t4[1];
                        bLo[1][0] = t4[2]; bLo[1][1] = t4[3];
                    }
#pragma unroll
                    for (int mi = 0; mi < 2; mi++)
#pragma unroll
                        for (int ni = 0; ni < 2; ni++) {
                            mma16816(acc[mi][ni], aHi[mi], bHi[ni]);
                            mma16816(acc[mi][ni], aLo[mi], bHi[ni]);
                            mma16816(acc[mi][ni], aHi[mi], bLo[ni]);
                        }
                }
                __syncthreads();
            }

            // stage acc -> Cs
            const int g = lane >> 2, tg = lane & 3;
#pragma unroll
            for (int mi = 0; mi < 2; mi++)
#pragma unroll
                for (int half = 0; half < 2; half++) {
                    const int r = wm + mi * 16 + g + half * 8;
#pragma unroll
                    for (int ni = 0; ni < 2; ni++) {
                        const int cc = wn + ni * 8 + tg * 2;
                        float2 v;
                        v.x = acc[mi][ni][half * 2 + 0];
                        v.y = acc[mi][ni][half * 2 + 1];
                        *reinterpret_cast<float2*>(&Cs[r * 36 + cc]) = v;
                    }
                }
            __syncthreads();
        }

        // ---- fused cell update: 2 threads per batch row, 4 hidden units each ----
        {
            const int b = tid >> 1, hs = (tid & 1) * 4;
            const int j0 = blk * 8;
            const float* gp   = g_gpre + ((size_t)t * BATCH + b) * G4;
            const float* cold = g_cbuf + (size_t)(t & 1) * BATCH * HID + (size_t)b * HID;
            float*       cnew = g_cbuf + (size_t)((t + 1) & 1) * BATCH * HID + (size_t)b * HID;
            __nv_bfloat16* hh = g_hhi + ((size_t)t * BATCH + b) * HID;
            __nv_bfloat16* hl = g_hlo + ((size_t)t * BATCH + b) * HID;

            const float4 pi = *reinterpret_cast<const float4*>(gp + 0 * HID + j0 + hs);
            const float4 pf = *reinterpret_cast<const float4*>(gp + 1 * HID + j0 + hs);
            const float4 pg = *reinterpret_cast<const float4*>(gp + 2 * HID + j0 + hs);
            const float4 po = *reinterpret_cast<const float4*>(gp + 3 * HID + j0 + hs);
            float4 co = make_float4(0.f, 0.f, 0.f, 0.f);
            if (t > 0) co = *reinterpret_cast<const float4*>(cold + j0 + hs);

            float cn[4], hn[4];
#pragma unroll
            for (int q = 0; q < 4; q++) {
                float ai = 0.f, af = 0.f, ag = 0.f, ao = 0.f;
                if (t > 0) {
                    ai = Cs[b * 36 + 0  + hs + q];
                    af = Cs[b * 36 + 8  + hs + q];
                    ag = Cs[b * 36 + 16 + hs + q];
                    ao = Cs[b * 36 + 24 + hs + q];
                }
                const float* pip = &pi.x; const float* pfp = &pf.x;
                const float* pgp = &pg.x; const float* pop = &po.x;
                const float* cop = &co.x;
                const float gi = 1.f / (1.f + expf(-(ai + pip[q])));
                const float gf = 1.f / (1.f + expf(-(af + pfp[q])));
                const float gg = tanhf(ag + pgp[q]);
                const float go = 1.f / (1.f + expf(-(ao + pop[q])));
                const float cv = gf * cop[q] + gi * gg;
                cn[q] = cv;
                hn[q] = go * tanhf(cv);
            }
            *reinterpret_cast<float4*>(cnew + j0 + hs) = make_float4(cn[0], cn[1], cn[2], cn[3]);
            __nv_bfloat16 h0, l0, h1, l1, h2, l2, h3, l3;
            split1(hn[0], h0, l0); split1(hn[1], h1, l1);
            split1(hn[2], h2, l2); split1(hn[3], h3, l3);
            *reinterpret_cast<uint2*>(hh + j0 + hs) = make_uint2(pack2(h0, h1), pack2(h2, h3));
            *reinterpret_cast<uint2*>(hl + j0 + hs) = make_uint2(pack2(l0, l1), pack2(l2, l3));
        }

        // ---- inter-step barrier (release: fence+arrive, acquire: spin+fence) ----
        if (t + 1 < SEQT) {
            __threadfence();
            __syncthreads();
            if (tid == 0) {
                atomicAdd(&g_bar[t], 1);
                while (((volatile int*)g_bar)[t] < gridDim.x) {}
            }
            __syncthreads();
            __threadfence();
        }
    }
}

// ---------------- launch ------------------------------------------------------
extern "C" void kernel_launch(void* const* d_in, const int* in_sizes, int n_in,
                              void* d_out, int out_size) {
    const float* enc  = (const float*)d_in[0];
    const int*   caps = (const int*  )d_in[1];
    const float* emb  = (const float*)d_in[2];
    const float* Wih  = (const float*)d_in[3];
    const float* Whh  = (const float*)d_in[4];
    const float* bih  = (const float*)d_in[5];
    const float* bhh  = (const float*)d_in[6];
    const float* Wfc  = (const float*)d_in[7];
    const float* bfc  = (const float*)d_in[8];
    float* out = (float*)d_out;

    cudaFuncSetAttribute(mma_gemm<0>, cudaFuncAttributeMaxDynamicSharedMemorySize, SMEMSZ);
    cudaFuncSetAttribute(mma_gemm<1>, cudaFuncAttributeMaxDynamicSharedMemorySize, SMEMSZ);
    cudaFuncSetAttribute(lstm_persistent, cudaFuncAttributeMaxDynamicSharedMemorySize, SMEMSZ_P);

    void* p;
#define SYM(v, s) cudaGetSymbolAddress(&p, s); __nv_bfloat16* v = (__nv_bfloat16*)p;
    SYM(xhi, g_xhi)       SYM(xlo, g_xlo)
    SYM(wih_hi, g_wih_hi) SYM(wih_lo, g_wih_lo)
    SYM(wfc_hi, g_wfc_hi) SYM(wfc_lo, g_wfc_lo)
    SYM(hhi, g_hhi)       SYM(hlo, g_hlo)
#undef SYM
    cudaGetSymbolAddress(&p, g_gpre);
    float* gpre = (float*)p;

    gather_split<<<MALL, 128>>>(enc, caps, emb);        // also zeros g_bar
    split_plain4<<<1024, 256>>>(Wih, wih_hi, wih_lo, G4 * EMB / 4);
    split_whh4<<<2048, 256>>>(Whh);
    split_wfc4<<<2048, 256>>>(Wfc);

    // input projection: G_pre = X @ W_ih^T + b_ih + b_hh   [3072, 4096]
    mma_gemm<0><<<dim3(G4 / 128, MALL / 128), 256, SMEMSZ>>>(
        xhi, xlo, wih_hi, wih_lo, bih, bhh, gpre, EMB, G4);

    // full recurrence in one persistent kernel
    lstm_persistent<<<128, 256, SMEMSZ_P>>>();

    // FC: logits[b,t,:] = h @ W_fc^T + b_fc   (N padded to 12032, guarded)
    mma_gemm<1><<<dim3(VOCP / 128, MALL / 128), 256, SMEMSZ>>>(
        hhi, hlo, wfc_hi, wfc_lo, bfc, nullptr, out, HID, VOC);
}

// round 11
// speedup vs baseline: 1.5705x; 1.5705x over previous
#include <cuda_runtime.h>
#include <cuda_bf16.h>
#include <cuda_fp16.h>
#include <math.h>
#include <stdint.h>

constexpr int BATCH = 128, SEQT = 24, EMB = 512, HID = 1024, VOC = 12000;
constexpr int MALL = SEQT * BATCH;     // 3072, row m = t*128 + b
constexpr int G4 = 4 * HID;            // 4096
constexpr int VOCP = 12032;            // VOC padded to 128
constexpr int BK = 32;                 // K chunk
constexpr int LDT = 40;                // padded smem row stride (16-bit elems)
constexpr int STAGES = 3;
constexpr int TA = 128 * LDT;          // A tile elems (rows always 128)
constexpr uint32_t SMEMSZ   = STAGES * (2 * TA + 2 * 128 * LDT) * 2;  // 122880 B (bf16x3 GEMM)
constexpr uint32_t SMEMSZ_L = STAGES * (2 * TA + 2 * 32 * LDT) * 2;   // 76800 B (lstm)
constexpr uint32_t SMEMSZ_F = STAGES * (2 * TA) * 2;                  // 61440 B (fp16 FC)

// ---------------- device scratch (allocation forbidden) ---------------------
__device__ __nv_bfloat16 g_xhi[(size_t)MALL * EMB],  g_xlo[(size_t)MALL * EMB];
__device__ __nv_bfloat16 g_wih_hi[(size_t)G4 * EMB], g_wih_lo[(size_t)G4 * EMB];
__device__ __nv_bfloat16 g_whh_hi[(size_t)G4 * HID], g_whh_lo[(size_t)G4 * HID]; // interleaved
__device__ __half        g_wfcf[(size_t)VOCP * HID];  // fp16 single-term FC weights
__device__ __nv_bfloat16 g_hhi[(size_t)MALL * HID],  g_hlo[(size_t)MALL * HID];
__device__ __half        g_hf16[(size_t)MALL * HID];  // fp16 h for FC
__device__ float g_gpre[(size_t)MALL * G4];
__device__ float g_cbuf[2 * BATCH * HID];

// ---------------- helpers ----------------------------------------------------
__device__ __forceinline__ uint32_t smem_u32(const void* p) {
    uint32_t a;
    asm("{ .reg .u64 t; cvta.to.shared.u64 t, %1; cvt.u32.u64 %0, t; }" : "=r"(a) : "l"(p));
    return a;
}
__device__ __forceinline__ void cp16(uint32_t d, const void* s) {
    asm volatile("cp.async.cg.shared.global [%0], [%1], 16;" :: "r"(d), "l"(s));
}
__device__ __forceinline__ void cp_commit() { asm volatile("cp.async.commit_group;"); }
template <int N> __device__ __forceinline__ void cp_wait() {
    asm volatile("cp.async.wait_group %0;" :: "n"(N));
}
__device__ __forceinline__ void ldsm4(uint32_t* r, uint32_t a) {
    asm volatile("ldmatrix.sync.aligned.m8n8.x4.shared.b16 {%0,%1,%2,%3}, [%4];"
                 : "=r"(r[0]), "=r"(r[1]), "=r"(r[2]), "=r"(r[3]) : "r"(a));
}
__device__ __forceinline__ void mma16816(float* d, const uint32_t* a, const uint32_t* b) {
    asm volatile("mma.sync.aligned.m16n8k16.row.col.f32.bf16.bf16.f32 "
                 "{%0,%1,%2,%3}, {%4,%5,%6,%7}, {%8,%9}, {%0,%1,%2,%3};"
                 : "+f"(d[0]), "+f"(d[1]), "+f"(d[2]), "+f"(d[3])
                 : "r"(a[0]), "r"(a[1]), "r"(a[2]), "r"(a[3]), "r"(b[0]), "r"(b[1]));
}
__device__ __forceinline__ void mma16816h(float* d, const uint32_t* a, const uint32_t* b) {
    asm volatile("mma.sync.aligned.m16n8k16.row.col.f32.f16.f16.f32 "
                 "{%0,%1,%2,%3}, {%4,%5,%6,%7}, {%8,%9}, {%0,%1,%2,%3};"
                 : "+f"(d[0]), "+f"(d[1]), "+f"(d[2]), "+f"(d[3])
                 : "r"(a[0]), "r"(a[1]), "r"(a[2]), "r"(a[3]), "r"(b[0]), "r"(b[1]));
}
__device__ __forceinline__ void split1(float x, __nv_bfloat16& hi, __nv_bfloat16& lo) {
    hi = __float2bfloat16(x);
    lo = __float2bfloat16(x - __bfloat162float(hi));
}
__device__ __forceinline__ uint32_t pack2(__nv_bfloat16 a, __nv_bfloat16 b) {
    __nv_bfloat162 p = __halves2bfloat162(a, b);
    return *reinterpret_cast<uint32_t*>(&p);
}
__device__ __forceinline__ void split4(float4 v, uint2& hi, uint2& lo) {
    __nv_bfloat16 h0, l0, h1, l1, h2, l2, h3, l3;
    split1(v.x, h0, l0); split1(v.y, h1, l1);
    split1(v.z, h2, l2); split1(v.w, h3, l3);
    hi = make_uint2(pack2(h0, h1), pack2(h2, h3));
    lo = make_uint2(pack2(l0, l1), pack2(l2, l3));
}

// ---------------- preprocessing (vectorized) ----------------------------------
__global__ void split_plain4(const float* __restrict__ s, __nv_bfloat16* __restrict__ hi,
                             __nv_bfloat16* __restrict__ lo, int n4) {
    for (int i = blockIdx.x * blockDim.x + threadIdx.x; i < n4; i += gridDim.x * blockDim.x) {
        uint2 uh, ul;
        split4(reinterpret_cast<const float4*>(s)[i], uh, ul);
        reinterpret_cast<uint2*>(hi)[i] = uh;
        reinterpret_cast<uint2*>(lo)[i] = ul;
    }
}
// W_hh interleave: dst row d -> blk=d>>5, gate=(d>>3)&3, j=d&7 ;
// src row = gate*HID + blk*8 + j
__global__ void split_whh4(const float* __restrict__ s) {
    constexpr int N4 = G4 * HID / 4;
    for (int i = blockIdx.x * blockDim.x + threadIdx.x; i < N4; i += gridDim.x * blockDim.x) {
        const int d = i >> 8, k4 = i & 255;
        const int src = ((d >> 3) & 3) * HID + (d >> 5) * 8 + (d & 7);
        uint2 uh, ul;
        split4(*reinterpret_cast<const float4*>(s + (size_t)src * HID + k4 * 4), uh, ul);
        reinterpret_cast<uint2*>(g_whh_hi)[i] = uh;
        reinterpret_cast<uint2*>(g_whh_lo)[i] = ul;
    }
}
__global__ void cvt_wfc_f16(const float* __restrict__ s) {
    constexpr int N4 = VOCP * HID / 4;
    for (int i = blockIdx.x * blockDim.x + threadIdx.x; i < N4; i += gridDim.x * blockDim.x) {
        const int r = i >> 8;
        float4 v = (r < VOC) ? reinterpret_cast<const float4*>(s)[i]
                             : make_float4(0.f, 0.f, 0.f, 0.f);
        __half2 a = __floats2half2_rn(v.x, v.y);
        __half2 b = __floats2half2_rn(v.z, v.w);
        reinterpret_cast<uint2*>(g_wfcf)[i] =
            make_uint2(*reinterpret_cast<uint32_t*>(&a), *reinterpret_cast<uint32_t*>(&b));
    }
}
__global__ void gather_split(const float* __restrict__ enc, const int* __restrict__ caps,
                             const float* __restrict__ emb) {
    const int m = blockIdx.x, t = m >> 7, b = m & 127;
    const float* src = (t == 0) ? enc + (size_t)b * EMB
                                : emb + (size_t)caps[b * SEQT + (t - 1)] * EMB;
    const float4 v = reinterpret_cast<const float4*>(src)[threadIdx.x];
    const int i = m * (EMB / 4) + threadIdx.x;
    uint2 uh, ul;
    split4(v, uh, ul);
    reinterpret_cast<uint2*>(g_xhi)[i] = uh;
    reinterpret_cast<uint2*>(g_xlo)[i] = ul;
}

// ---------------- bf16x3 mainloop: acc += 3-term A[128xK] @ B[NTxK]^T --------
// 256 threads, 8 warps. NT=128: 2Mx4N (wt 64x32). NT=32: 4Mx2N (wt 32x16).
template <int NT, int MI, int NI>
__device__ __forceinline__ void gemm_main(
    const __nv_bfloat16* __restrict__ Ahi, const __nv_bfloat16* __restrict__ Alo,
    const __nv_bfloat16* __restrict__ Bhi, const __nv_bfloat16* __restrict__ Blo,
    int m0, int n0, int K, uint32_t sm, float (&acc)[MI][NI][4]) {
    constexpr int TB = NT * LDT;
    constexpr int STAGE = 2 * TA + 2 * TB;
    constexpr int TOT = (128 * 2 + NT * 2) * 4;

    const int tid = threadIdx.x, warp = tid >> 5, lane = tid & 31;
    const int wm = (NT == 128) ? (warp & 1) * 64 : (warp & 3) * 32;
    const int wn = (NT == 128) ? (warp >> 1) * 32 : (warp >> 2) * 16;
    const int l8 = lane & 7, lt = lane >> 3;
    const int nk = K / BK;

    auto load_stage = [&](int stage, int k0) {
        const uint32_t sbase = sm + stage * STAGE * 2;
#pragma unroll
        for (int idx = tid; idx < TOT; idx += 256) {
            uint32_t dst;
            const __nv_bfloat16* src;
            if (idx < 512) {
                const int r = idx >> 2, c = idx & 3;
                dst = sbase + (r * LDT + c * 8) * 2;
                src = Ahi + (size_t)(m0 + r) * K + k0 + c * 8;
            } else if (idx < 1024) {
                const int j = idx - 512, r = j >> 2, c = j & 3;
                dst = sbase + (TA + r * LDT + c * 8) * 2;
                src = Alo + (size_t)(m0 + r) * K + k0 + c * 8;
            } else if (idx < 1024 + NT * 4) {
                const int j = idx - 1024, r = j >> 2, c = j & 3;
                dst = sbase + (2 * TA + r * LDT + c * 8) * 2;
                src = Bhi + (size_t)(n0 + r) * K + k0 + c * 8;
            } else {
                const int j = idx - 1024 - NT * 4, r = j >> 2, c = j & 3;
                dst = sbase + (2 * TA + TB + r * LDT + c * 8) * 2;
                src = Blo + (size_t)(n0 + r) * K + k0 + c * 8;
            }
            cp16(dst, src);
        }
        cp_commit();
    };

    load_stage(0, 0);
    load_stage(1, BK);

    for (int kc = 0; kc < nk; kc++) {
        if (kc == nk - 1) cp_wait<0>(); else cp_wait<1>();
        __syncthreads();
        if (kc + STAGES - 1 < nk)
            load_stage((kc + STAGES - 1) % STAGES, (kc + STAGES - 1) * BK);
        const uint32_t sb = sm + (kc % STAGES) * STAGE * 2;
#pragma unroll
        for (int h = 0; h < 2; h++) {
            const int kk = h * 16;
            uint32_t aHi[MI][4], aLo[MI][4], bHi[NI][2], bLo[NI][2];
#pragma unroll
            for (int mi = 0; mi < MI; mi++) {
                const uint32_t ra = sb +
                    ((wm + mi * 16 + l8 + (lt & 1) * 8) * LDT + kk + (lt >> 1) * 8) * 2;
                ldsm4(aHi[mi], ra);
                ldsm4(aLo[mi], ra + TA * 2);
            }
#pragma unroll
            for (int nj = 0; nj < NI / 2; nj++) {
                const uint32_t rb = sb + 2 * TA * 2 +
                    ((wn + nj * 16 + l8 + (lt >> 1) * 8) * LDT + kk + (lt & 1) * 8) * 2;
                uint32_t t4[4];
                ldsm4(t4, rb);
                bHi[nj * 2][0] = t4[0]; bHi[nj * 2][1] = t4[1];
                bHi[nj * 2 + 1][0] = t4[2]; bHi[nj * 2 + 1][1] = t4[3];
                ldsm4(t4, rb + TB * 2);
                bLo[nj * 2][0] = t4[0]; bLo[nj * 2][1] = t4[1];
                bLo[nj * 2 + 1][0] = t4[2]; bLo[nj * 2 + 1][1] = t4[3];
            }
#pragma unroll
            for (int mi = 0; mi < MI; mi++)
#pragma unroll
                for (int ni = 0; ni < NI; ni++) {
                    mma16816(acc[mi][ni], aHi[mi], bHi[ni]);
                    mma16816(acc[mi][ni], aLo[mi], bHi[ni]);
                    mma16816(acc[mi][ni], aHi[mi], bLo[ni]);
                }
        }
    }
    __syncthreads();
}

// ---------------- input-proj GEMM (bf16x3): C = A @ B^T + b1 + b2 ------------
__global__ __launch_bounds__(256, 1)
void mma_gemm0(const __nv_bfloat16* __restrict__ Ahi, const __nv_bfloat16* __restrict__ Alo,
               const __nv_bfloat16* __restrict__ Bhi, const __nv_bfloat16* __restrict__ Blo,
               const float* __restrict__ b1, const float* __restrict__ b2,
               float* __restrict__ C, int K, int N) {
    extern __shared__ char smraw[];
    float acc[4][4][4];
#pragma unroll
    for (int a = 0; a < 4; a++)
#pragma unroll
        for (int b = 0; b < 4; b++)
#pragma unroll
            for (int c = 0; c < 4; c++) acc[a][b][c] = 0.f;

    const int m0 = blockIdx.y * 128, n0 = blockIdx.x * 128;
    gemm_main<128, 4, 4>(Ahi, Alo, Bhi, Blo, m0, n0, K, smem_u32(smraw), acc);

    const int lane = threadIdx.x & 31, warp = threadIdx.x >> 5;
    const int wm = (warp & 1) * 64, wn = (warp >> 1) * 32;
    const int g = lane >> 2, tg = lane & 3;
#pragma unroll
    for (int mi = 0; mi < 4; mi++)
#pragma unroll
        for (int half = 0; half < 2; half++) {
            const int m = m0 + wm + mi * 16 + g + half * 8;
            const size_t rowBase = (size_t)m * N;
#pragma unroll
            for (int ni = 0; ni < 4; ni++) {
                const int n = n0 + wn + ni * 8 + tg * 2;
                const float2 bb = *reinterpret_cast<const float2*>(b1 + n);
                const float2 b2v = *reinterpret_cast<const float2*>(b2 + n);
                float2 v;
                v.x = acc[mi][ni][half * 2 + 0] + bb.x + b2v.x;
                v.y = acc[mi][ni][half * 2 + 1] + bb.y + b2v.y;
                *reinterpret_cast<float2*>(C + rowBase + n) = v;
            }
        }
}

// ---------------- FC GEMM: single-term fp16, logits reorder + bias -----------
// C[(b*24+t), n] = sum_k h_f16[m,k] * Wfc_f16[n,k] + b_fc[n], m = t*128+b
__global__ __launch_bounds__(256, 2)
void fc_gemm(const __half* __restrict__ A, const __half* __restrict__ B,
             const float* __restrict__ b1, float* __restrict__ C, int K, int N) {
    extern __shared__ char smraw[];
    const uint32_t sm = smem_u32(smraw);
    constexpr int STAGE = 2 * TA;
    float acc[4][4][4];
#pragma unroll
    for (int a = 0; a < 4; a++)
#pragma unroll
        for (int b = 0; b < 4; b++)
#pragma unroll
            for (int c = 0; c < 4; c++) acc[a][b][c] = 0.f;

    const int tid = threadIdx.x, warp = tid >> 5, lane = tid & 31;
    const int m0 = blockIdx.y * 128, n0 = blockIdx.x * 128;
    const int wm = (warp & 1) * 64, wn = (warp >> 1) * 32;
    const int l8 = lane & 7, lt = lane >> 3;
    const int nk = K / BK;

    auto load_stage = [&](int stage, int k0) {
        const uint32_t sbase = sm + stage * STAGE * 2;
#pragma unroll
        for (int q = 0; q < 4; q++) {
            const int idx = q * 256 + tid;
            const int tile = idx >> 9, rem = idx & 511, r = rem >> 2, c = rem & 3;
            const uint32_t dst = sbase + (tile * TA + r * LDT + c * 8) * 2;
            const __half* src = (tile ? B : A) + (size_t)((tile ? n0 : m0) + r) * K + k0 + c * 8;
            cp16(dst, src);
        }
        cp_commit();
    };

    load_stage(0, 0);
    load_stage(1, BK);

    for (int kc = 0; kc < nk; kc++) {
        if (kc == nk - 1) cp_wait<0>(); else cp_wait<1>();
        __syncthreads();
        if (kc + STAGES - 1 < nk)
            load_stage((kc + STAGES - 1) % STAGES, (kc + STAGES - 1) * BK);
        const uint32_t sb = sm + (kc % STAGES) * STAGE * 2;
#pragma unroll
        for (int h = 0; h < 2; h++) {
            const int kk = h * 16;
            uint32_t af[4][4], bf[4][2];
#pragma unroll
            for (int mi = 0; mi < 4; mi++) {
                const uint32_t ra = sb +
                    ((wm + mi * 16 + l8 + (lt & 1) * 8) * LDT + kk + (lt >> 1) * 8) * 2;
                ldsm4(af[mi], ra);
            }
#pragma unroll
            for (int nj = 0; nj < 2; nj++) {
                const uint32_t rb = sb + TA * 2 +
                    ((wn + nj * 16 + l8 + (lt >> 1) * 8) * LDT + kk + (lt & 1) * 8) * 2;
                uint32_t t4[4];
                ldsm4(t4, rb);
                bf[nj * 2][0] = t4[0]; bf[nj * 2][1] = t4[1];
                bf[nj * 2 + 1][0] = t4[2]; bf[nj * 2 + 1][1] = t4[3];
            }
#pragma unroll
            for (int mi = 0; mi < 4; mi++)
#pragma unroll
                for (int ni = 0; ni < 4; ni++)
                    mma16816h(acc[mi][ni], af[mi], bf[ni]);
        }
    }
    __syncthreads();

    const int g = lane >> 2, tg = lane & 3;
#pragma unroll
    for (int mi = 0; mi < 4; mi++)
#pragma unroll
        for (int half = 0; half < 2; half++) {
            const int m = m0 + wm + mi * 16 + g + half * 8;
            const size_t rowBase = ((size_t)(m & 127) * SEQT + (size_t)(m >> 7)) * N;
#pragma unroll
            for (int ni = 0; ni < 4; ni++) {
                const int n = n0 + wn + ni * 8 + tg * 2;
                if (n >= N) continue;
                const float2 bb = *reinterpret_cast<const float2*>(b1 + n);
                float2 v;
                v.x = acc[mi][ni][half * 2 + 0] + bb.x;
                v.y = acc[mi][ni][half * 2 + 1] + bb.y;
                *reinterpret_cast<float2*>(C + rowBase + n) = v;
            }
        }
}

// ---------------- recurrent step: 128 CTAs, tile [128 x 32], fused cell ------
// CTA blk owns hidden [blk*8, blk*8+8) x 4 gates; D col c = gate*8 + j.
__global__ __launch_bounds__(256, 1)
void lstm_mma_step(int t) {
    extern __shared__ char smraw[];
    const int tid = threadIdx.x, blk = blockIdx.x;
    float* Cs = reinterpret_cast<float*>(smraw);   // [128][36]

    if (t > 0) {
        float acc[2][2][4] = {};
        gemm_main<32, 2, 2>(g_hhi + (size_t)(t - 1) * BATCH * HID,
                            g_hlo + (size_t)(t - 1) * BATCH * HID,
                            g_whh_hi, g_whh_lo, 0, blk * 32, HID,
                            smem_u32(smraw), acc);
        const int lane = tid & 31, warp = tid >> 5;
        const int wm = (warp & 3) * 32, wn = (warp >> 2) * 16;
        const int g = lane >> 2, tg = lane & 3;
#pragma unroll
        for (int mi = 0; mi < 2; mi++)
#pragma unroll
            for (int half = 0; half < 2; half++) {
                const int r = wm + mi * 16 + g + half * 8;
#pragma unroll
                for (int ni = 0; ni < 2; ni++) {
                    const int c = wn + ni * 8 + tg * 2;
                    float2 v;
                    v.x = acc[mi][ni][half * 2 + 0];
                    v.y = acc[mi][ni][half * 2 + 1];
                    *reinterpret_cast<float2*>(&Cs[r * 36 + c]) = v;
                }
            }
        __syncthreads();
    }

    // cell update: 2 threads per batch row, 4 hidden units each
    const int b = tid >> 1, hs = (tid & 1) * 4;
    const int j0 = blk * 8;
    const float* gp   = g_gpre + ((size_t)t * BATCH + b) * G4;
    const float* cold = g_cbuf + (size_t)(t & 1) * BATCH * HID + (size_t)b * HID;
    float*       cnew = g_cbuf + (size_t)((t + 1) & 1) * BATCH * HID + (size_t)b * HID;
    __nv_bfloat16* hh = g_hhi + ((size_t)t * BATCH + b) * HID;
    __nv_bfloat16* hl = g_hlo + ((size_t)t * BATCH + b) * HID;
    __half*        hf = g_hf16 + ((size_t)t * BATCH + b) * HID;

    const float4 pi = *reinterpret_cast<const float4*>(gp + 0 * HID + j0 + hs);
    const float4 pf = *reinterpret_cast<const float4*>(gp + 1 * HID + j0 + hs);
    const float4 pg = *reinterpret_cast<const float4*>(gp + 2 * HID + j0 + hs);
    const float4 po = *reinterpret_cast<const float4*>(gp + 3 * HID + j0 + hs);
    float4 co = make_float4(0.f, 0.f, 0.f, 0.f);
    if (t > 0) co = *reinterpret_cast<const float4*>(cold + j0 + hs);

    float cn[4], hn[4];
#pragma unroll
    for (int q = 0; q < 4; q++) {
        float ai = 0.f, af = 0.f, ag = 0.f, ao = 0.f;
        if (t > 0) {
            ai = Cs[b * 36 + 0  + hs + q];
            af = Cs[b * 36 + 8  + hs + q];
            ag = Cs[b * 36 + 16 + hs + q];
            ao = Cs[b * 36 + 24 + hs + q];
        }
        const float* pip = &pi.x; const float* pfp = &pf.x;
        const float* pgp = &pg.x; const float* pop = &po.x;
        const float* cop = &co.x;
        const float gi = 1.f / (1.f + expf(-(ai + pip[q])));
        const float gf = 1.f / (1.f + expf(-(af + pfp[q])));
        const float gg = tanhf(ag + pgp[q]);
        const float go = 1.f / (1.f + expf(-(ao + pop[q])));
        const float cv = gf * cop[q] + gi * gg;
        cn[q] = cv;
        hn[q] = go * tanhf(cv);
    }
    *reinterpret_cast<float4*>(cnew + j0 + hs) = make_float4(cn[0], cn[1], cn[2], cn[3]);
    __nv_bfloat16 h0, l0, h1, l1, h2, l2, h3, l3;
    split1(hn[0], h0, l0); split1(hn[1], h1, l1);
    split1(hn[2], h2, l2); split1(hn[3], h3, l3);
    *reinterpret_cast<uint2*>(hh + j0 + hs) = make_uint2(pack2(h0, h1), pack2(h2, h3));
    *reinterpret_cast<uint2*>(hl + j0 + hs) = make_uint2(pack2(l0, l1), pack2(l2, l3));
    __half2 f01 = __floats2half2_rn(hn[0], hn[1]);
    __half2 f23 = __floats2half2_rn(hn[2], hn[3]);
    *reinterpret_cast<uint2*>(hf + j0 + hs) =
        make_uint2(*reinterpret_cast<uint32_t*>(&f01), *reinterpret_cast<uint32_t*>(&f23));
}

// ---------------- launch ------------------------------------------------------
extern "C" void kernel_launch(void* const* d_in, const int* in_sizes, int n_in,
                              void* d_out, int out_size) {
    const float* enc  = (const float*)d_in[0];
    const int*   caps = (const int*  )d_in[1];
    const float* emb  = (const float*)d_in[2];
    const float* Wih  = (const float*)d_in[3];
    const float* Whh  = (const float*)d_in[4];
    const float* bih  = (const float*)d_in[5];
    const float* bhh  = (const float*)d_in[6];
    const float* Wfc  = (const float*)d_in[7];
    const float* bfc  = (const float*)d_in[8];
    float* out = (float*)d_out;

    cudaFuncSetAttribute(mma_gemm0, cudaFuncAttributeMaxDynamicSharedMemorySize, SMEMSZ);
    cudaFuncSetAttribute(fc_gemm, cudaFuncAttributeMaxDynamicSharedMemorySize, SMEMSZ_F);
    cudaFuncSetAttribute(lstm_mma_step, cudaFuncAttributeMaxDynamicSharedMemorySize, SMEMSZ_L);

    void* p;
#define SYM(v, s) cudaGetSymbolAddress(&p, s); __nv_bfloat16* v = (__nv_bfloat16*)p;
    SYM(xhi, g_xhi)       SYM(xlo, g_xlo)
    SYM(wih_hi, g_wih_hi) SYM(wih_lo, g_wih_lo)
#undef SYM
    cudaGetSymbolAddress(&p, g_gpre);  float*  gpre = (float*)p;
    cudaGetSymbolAddress(&p, g_hf16);  __half* hf16 = (__half*)p;
    cudaGetSymbolAddress(&p, g_wfcf);  __half* wfcf = (__half*)p;

    gather_split<<<MALL, 128>>>(enc, caps, emb);
    split_plain4<<<1024, 256>>>(Wih, wih_hi, wih_lo, G4 * EMB / 4);
    split_whh4<<<2048, 256>>>(Whh);
    cvt_wfc_f16<<<2048, 256>>>(Wfc);

    // input projection: G_pre = X @ W_ih^T + b_ih + b_hh   [3072, 4096]
    mma_gemm0<<<dim3(G4 / 128, MALL / 128), 256, SMEMSZ>>>(
        xhi, xlo, wih_hi, wih_lo, bih, bhh, gpre, EMB, G4);

    for (int t = 0; t < SEQT; t++)
        lstm_mma_step<<<128, 256, SMEMSZ_L>>>(t);

    // FC: logits[b,t,:] = h @ W_fc^T + b_fc   (fp16 single-term, N guarded)
    fc_gemm<<<dim3(VOCP / 128, MALL / 128), 256, SMEMSZ_F>>>(
        hf16, wfcf, bfc, out, HID, VOC);
}

// round 12
// speedup vs baseline: 2.3262x; 1.4812x over previous
#include <cuda_runtime.h>
#include <cuda_bf16.h>
#include <cuda_fp16.h>
#include <math.h>
#include <stdint.h>

constexpr int BATCH = 128, SEQT = 24, EMB = 512, HID = 1024, VOC = 12000;
constexpr int MALL = SEQT * BATCH;     // 3072, row m = t*128 + b
constexpr int G4 = 4 * HID;            // 4096
constexpr int VOCP = 12032;            // VOC padded to 128
constexpr int BK = 32;                 // K chunk
constexpr int LDT = 40;                // padded smem row stride (16-bit elems)
constexpr int STAGES = 3;
constexpr int TA = 128 * LDT;          // A tile elems (rows always 128)
constexpr uint32_t SMEMSZ_128 = STAGES * (TA + 128 * LDT) * 2;  // 61440 B
constexpr uint32_t SMEMSZ_32  = STAGES * (TA + 32 * LDT) * 2;   // 38400 B

// ---------------- device scratch (allocation forbidden) ---------------------
__device__ __half g_xf[(size_t)MALL * EMB];
__device__ __half g_wihf[(size_t)G4 * EMB];
__device__ __half g_whhf[(size_t)G4 * HID];   // gate-interleaved rows
__device__ __half g_wfcf[(size_t)VOCP * HID];
__device__ __half g_hf16[(size_t)MALL * HID];
__device__ float g_gpre[(size_t)MALL * G4];
__device__ float g_cbuf[2 * BATCH * HID];

// ---------------- helpers ----------------------------------------------------
__device__ __forceinline__ uint32_t smem_u32(const void* p) {
    uint32_t a;
    asm("{ .reg .u64 t; cvta.to.shared.u64 t, %1; cvt.u32.u64 %0, t; }" : "=r"(a) : "l"(p));
    return a;
}
__device__ __forceinline__ void cp16(uint32_t d, const void* s) {
    asm volatile("cp.async.cg.shared.global [%0], [%1], 16;" :: "r"(d), "l"(s));
}
__device__ __forceinline__ void cp_commit() { asm volatile("cp.async.commit_group;"); }
template <int N> __device__ __forceinline__ void cp_wait() {
    asm volatile("cp.async.wait_group %0;" :: "n"(N));
}
__device__ __forceinline__ void ldsm4(uint32_t* r, uint32_t a) {
    asm volatile("ldmatrix.sync.aligned.m8n8.x4.shared.b16 {%0,%1,%2,%3}, [%4];"
                 : "=r"(r[0]), "=r"(r[1]), "=r"(r[2]), "=r"(r[3]) : "r"(a));
}
__device__ __forceinline__ void mma16816h(float* d, const uint32_t* a, const uint32_t* b) {
    asm volatile("mma.sync.aligned.m16n8k16.row.col.f32.f16.f16.f32 "
                 "{%0,%1,%2,%3}, {%4,%5,%6,%7}, {%8,%9}, {%0,%1,%2,%3};"
                 : "+f"(d[0]), "+f"(d[1]), "+f"(d[2]), "+f"(d[3])
                 : "r"(a[0]), "r"(a[1]), "r"(a[2]), "r"(a[3]), "r"(b[0]), "r"(b[1]));
}
__device__ __forceinline__ uint2 f16x4(float4 v) {
    __half2 a = __floats2half2_rn(v.x, v.y);
    __half2 b = __floats2half2_rn(v.z, v.w);
    return make_uint2(*reinterpret_cast<uint32_t*>(&a), *reinterpret_cast<uint32_t*>(&b));
}

// ---------------- preprocessing (vectorized) ----------------------------------
__global__ void cvt_plain_f16(const float* __restrict__ s, __half* __restrict__ d, int n4) {
    for (int i = blockIdx.x * blockDim.x + threadIdx.x; i < n4; i += gridDim.x * blockDim.x)
        reinterpret_cast<uint2*>(d)[i] = f16x4(reinterpret_cast<const float4*>(s)[i]);
}
// W_hh interleave: dst row d -> blk=d>>5, gate=(d>>3)&3, j=d&7 ;
// src row = gate*HID + blk*8 + j  (CTA blk owns hidden [blk*8,blk*8+8) x 4 gates)
__global__ void cvt_whh_f16(const float* __restrict__ s) {
    constexpr int N4 = G4 * HID / 4;
    for (int i = blockIdx.x * blockDim.x + threadIdx.x; i < N4; i += gridDim.x * blockDim.x) {
        const int d = i >> 8, k4 = i & 255;
        const int src = ((d >> 3) & 3) * HID + (d >> 5) * 8 + (d & 7);
        reinterpret_cast<uint2*>(g_whhf)[i] =
            f16x4(*reinterpret_cast<const float4*>(s + (size_t)src * HID + k4 * 4));
    }
}
__global__ void cvt_wfc_f16(const float* __restrict__ s) {
    constexpr int N4 = VOCP * HID / 4;
    for (int i = blockIdx.x * blockDim.x + threadIdx.x; i < N4; i += gridDim.x * blockDim.x) {
        const int r = i >> 8;
        float4 v = (r < VOC) ? reinterpret_cast<const float4*>(s)[i]
                             : make_float4(0.f, 0.f, 0.f, 0.f);
        reinterpret_cast<uint2*>(g_wfcf)[i] = f16x4(v);
    }
}
__global__ void gather_f16(const float* __restrict__ enc, const int* __restrict__ caps,
                           const float* __restrict__ emb) {
    const int m = blockIdx.x, t = m >> 7, b = m & 127;
    const float* src = (t == 0) ? enc + (size_t)b * EMB
                                : emb + (size_t)caps[b * SEQT + (t - 1)] * EMB;
    const float4 v = reinterpret_cast<const float4*>(src)[threadIdx.x];
    reinterpret_cast<uint2*>(g_xf)[m * (EMB / 4) + threadIdx.x] = f16x4(v);
}

// ---------------- fp16 single-term mainloop ----------------------------------
// acc += A[128xK] @ B[NTxK]^T. 256 threads, 8 warps.
// NT=128: 2Mx4N (wt 64x32, MI=NI=4).  NT=32: 4Mx2N (wt 32x16, MI=NI=2).
template <int NT, int MI, int NI>
__device__ __forceinline__ void gemm_main_h(
    const __half* __restrict__ A, const __half* __restrict__ B,
    int m0, int n0, int K, uint32_t sm, float (&acc)[MI][NI][4]) {
    constexpr int TB = NT * LDT;
    constexpr int STAGE = TA + TB;
    constexpr int TOT = (128 + NT) * 4;

    const int tid = threadIdx.x, warp = tid >> 5, lane = tid & 31;
    const int wm = (NT == 128) ? (warp & 1) * 64 : (warp & 3) * 32;
    const int wn = (NT == 128) ? (warp >> 1) * 32 : (warp >> 2) * 16;
    const int l8 = lane & 7, lt = lane >> 3;
    const int nk = K / BK;

    auto load_stage = [&](int stage, int k0) {
        const uint32_t sbase = sm + stage * STAGE * 2;
#pragma unroll
        for (int idx = tid; idx < TOT; idx += 256) {
            uint32_t dst;
            const __half* src;
            if (idx < 512) {
                const int r = idx >> 2, c = idx & 3;
                dst = sbase + (r * LDT + c * 8) * 2;
                src = A + (size_t)(m0 + r) * K + k0 + c * 8;
            } else {
                const int j = idx - 512, r = j >> 2, c = j & 3;
                dst = sbase + (TA + r * LDT + c * 8) * 2;
                src = B + (size_t)(n0 + r) * K + k0 + c * 8;
            }
            cp16(dst, src);
        }
        cp_commit();
    };

    load_stage(0, 0);
    load_stage(1, BK);

    for (int kc = 0; kc < nk; kc++) {
        if (kc == nk - 1) cp_wait<0>(); else cp_wait<1>();
        __syncthreads();
        if (kc + STAGES - 1 < nk)
            load_stage((kc + STAGES - 1) % STAGES, (kc + STAGES - 1) * BK);
        const uint32_t sb = sm + (kc % STAGES) * STAGE * 2;
#pragma unroll
        for (int h = 0; h < 2; h++) {
            const int kk = h * 16;
            uint32_t af[MI][4], bf[NI][2];
#pragma unroll
            for (int mi = 0; mi < MI; mi++) {
                const uint32_t ra = sb +
                    ((wm + mi * 16 + l8 + (lt & 1) * 8) * LDT + kk + (lt >> 1) * 8) * 2;
                ldsm4(af[mi], ra);
            }
#pragma unroll
            for (int nj = 0; nj < NI / 2; nj++) {
                const uint32_t rb = sb + TA * 2 +
                    ((wn + nj * 16 + l8 + (lt >> 1) * 8) * LDT + kk + (lt & 1) * 8) * 2;
                uint32_t t4[4];
                ldsm4(t4, rb);
                bf[nj * 2][0] = t4[0]; bf[nj * 2][1] = t4[1];
                bf[nj * 2 + 1][0] = t4[2]; bf[nj * 2 + 1][1] = t4[3];
            }
#pragma unroll
            for (int mi = 0; mi < MI; mi++)
#pragma unroll
                for (int ni = 0; ni < NI; ni++)
                    mma16816h(acc[mi][ni], af[mi], bf[ni]);
        }
    }
    __syncthreads();
}

// ---------------- input-proj GEMM: C = X @ Wih^T + b_ih + b_hh ---------------
__global__ __launch_bounds__(256, 2)
void ip_gemm(const __half* __restrict__ A, const __half* __restrict__ B,
             const float* __restrict__ b1, const float* __restrict__ b2,
             float* __restrict__ C, int K, int N) {
    extern __shared__ char smraw[];
    float acc[4][4][4];
#pragma unroll
    for (int a = 0; a < 4; a++)
#pragma unroll
        for (int b = 0; b < 4; b++)
#pragma unroll
            for (int c = 0; c < 4; c++) acc[a][b][c] = 0.f;

    const int m0 = blockIdx.y * 128, n0 = blockIdx.x * 128;
    gemm_main_h<128, 4, 4>(A, B, m0, n0, K, smem_u32(smraw), acc);

    const int lane = threadIdx.x & 31, warp = threadIdx.x >> 5;
    const int wm = (warp & 1) * 64, wn = (warp >> 1) * 32;
    const int g = lane >> 2, tg = lane & 3;
#pragma unroll
    for (int mi = 0; mi < 4; mi++)
#pragma unroll
        for (int half = 0; half < 2; half++) {
            const int m = m0 + wm + mi * 16 + g + half * 8;
            const size_t rowBase = (size_t)m * N;
#pragma unroll
            for (int ni = 0; ni < 4; ni++) {
                const int n = n0 + wn + ni * 8 + tg * 2;
                const float2 bb = *reinterpret_cast<const float2*>(b1 + n);
                const float2 b2v = *reinterpret_cast<const float2*>(b2 + n);
                float2 v;
                v.x = acc[mi][ni][half * 2 + 0] + bb.x + b2v.x;
                v.y = acc[mi][ni][half * 2 + 1] + bb.y + b2v.y;
                *reinterpret_cast<float2*>(C + rowBase + n) = v;
            }
        }
}

// ---------------- FC GEMM: logits reorder + bias -----------------------------
// C[(b*24+t), n] = sum_k h[m,k] * Wfc[n,k] + b_fc[n], m = t*128+b
__global__ __launch_bounds__(256, 2)
void fc_gemm(const __half* __restrict__ A, const __half* __restrict__ B,
             const float* __restrict__ b1, float* __restrict__ C, int K, int N) {
    extern __shared__ char smraw[];
    float acc[4][4][4];
#pragma unroll
    for (int a = 0; a < 4; a++)
#pragma unroll
        for (int b = 0; b < 4; b++)
#pragma unroll
            for (int c = 0; c < 4; c++) acc[a][b][c] = 0.f;

    const int m0 = blockIdx.y * 128, n0 = blockIdx.x * 128;
    gemm_main_h<128, 4, 4>(A, B, m0, n0, K, smem_u32(smraw), acc);

    const int lane = threadIdx.x & 31, warp = threadIdx.x >> 5;
    const int wm = (warp & 1) * 64, wn = (warp >> 1) * 32;
    const int g = lane >> 2, tg = lane & 3;
#pragma unroll
    for (int mi = 0; mi < 4; mi++)
#pragma unroll
        for (int half = 0; half < 2; half++) {
            const int m = m0 + wm + mi * 16 + g + half * 8;
            const size_t rowBase = ((size_t)(m & 127) * SEQT + (size_t)(m >> 7)) * N;
#pragma unroll
            for (int ni = 0; ni < 4; ni++) {
                const int n = n0 + wn + ni * 8 + tg * 2;
                if (n >= N) continue;
                const float2 bb = *reinterpret_cast<const float2*>(b1 + n);
                float2 v;
                v.x = acc[mi][ni][half * 2 + 0] + bb.x;
                v.y = acc[mi][ni][half * 2 + 1] + bb.y;
                *reinterpret_cast<float2*>(C + rowBase + n) = v;
            }
        }
}

// ---------------- recurrent step: 128 CTAs, tile [128 x 32], fused cell ------
// CTA blk owns hidden [blk*8, blk*8+8) x 4 gates; D col c = gate*8 + j.
__global__ __launch_bounds__(256, 1)
void lstm_mma_step(int t) {
    extern __shared__ char smraw[];
    const int tid = threadIdx.x, blk = blockIdx.x;
    float* Cs = reinterpret_cast<float*>(smraw);   // [128][36], reuses GEMM smem

    if (t > 0) {
        float acc[2][2][4] = {};
        gemm_main_h<32, 2, 2>(g_hf16 + (size_t)(t - 1) * BATCH * HID,
                              g_whhf, 0, blk * 32, HID, smem_u32(smraw), acc);
        const int lane = tid & 31, warp = tid >> 5;
        const int wm = (warp & 3) * 32, wn = (warp >> 2) * 16;
        const int g = lane >> 2, tg = lane & 3;
#pragma unroll
        for (int mi = 0; mi < 2; mi++)
#pragma unroll
            for (int half = 0; half < 2; half++) {
                const int r = wm + mi * 16 + g + half * 8;
#pragma unroll
                for (int ni = 0; ni < 2; ni++) {
                    const int c = wn + ni * 8 + tg * 2;
                    float2 v;
                    v.x = acc[mi][ni][half * 2 + 0];
                    v.y = acc[mi][ni][half * 2 + 1];
                    *reinterpret_cast<float2*>(&Cs[r * 36 + c]) = v;
                }
            }
        __syncthreads();
    }

    // cell update: 2 threads per batch row, 4 hidden units each
    const int b = tid >> 1, hs = (tid & 1) * 4;
    const int j0 = blk * 8;
    const float* gp   = g_gpre + ((size_t)t * BATCH + b) * G4;
    const float* cold = g_cbuf + (size_t)(t & 1) * BATCH * HID + (size_t)b * HID;
    float*       cnew = g_cbuf + (size_t)((t + 1) & 1) * BATCH * HID + (size_t)b * HID;
    __half*      hf   = g_hf16 + ((size_t)t * BATCH + b) * HID;

    const float4 pi = *reinterpret_cast<const float4*>(gp + 0 * HID + j0 + hs);
    const float4 pf = *reinterpret_cast<const float4*>(gp + 1 * HID + j0 + hs);
    const float4 pg = *reinterpret_cast<const float4*>(gp + 2 * HID + j0 + hs);
    const float4 po = *reinterpret_cast<const float4*>(gp + 3 * HID + j0 + hs);
    float4 co = make_float4(0.f, 0.f, 0.f, 0.f);
    if (t > 0) co = *reinterpret_cast<const float4*>(cold + j0 + hs);

    float cn[4], hn[4];
#pragma unroll
    for (int q = 0; q < 4; q++) {
        float ai = 0.f, af = 0.f, ag = 0.f, ao = 0.f;
        if (t > 0) {
            ai = Cs[b * 36 + 0  + hs + q];
            af = Cs[b * 36 + 8  + hs + q];
            ag = Cs[b * 36 + 16 + hs + q];
            ao = Cs[b * 36 + 24 + hs + q];
        }
        const float* pip = &pi.x; const float* pfp = &pf.x;
        const float* pgp = &pg.x; const float* pop = &po.x;
        const float* cop = &co.x;
        const float gi = 1.f / (1.f + expf(-(ai + pip[q])));
        const float gf = 1.f / (1.f + expf(-(af + pfp[q])));
        const float gg = tanhf(ag + pgp[q]);
        const float go = 1.f / (1.f + expf(-(ao + pop[q])));
        const float cv = gf * cop[q] + gi * gg;
        cn[q] = cv;
        hn[q] = go * tanhf(cv);
    }
    *reinterpret_cast<float4*>(cnew + j0 + hs) = make_float4(cn[0], cn[1], cn[2], cn[3]);
    *reinterpret_cast<uint2*>(hf + j0 + hs) =
        f16x4(make_float4(hn[0], hn[1], hn[2], hn[3]));
}

// ---------------- launch ------------------------------------------------------
extern "C" void kernel_launch(void* const* d_in, const int* in_sizes, int n_in,
                              void* d_out, int out_size) {
    const float* enc  = (const float*)d_in[0];
    const int*   caps = (const int*  )d_in[1];
    const float* emb  = (const float*)d_in[2];
    const float* Wih  = (const float*)d_in[3];
    const float* Whh  = (const float*)d_in[4];
    const float* bih  = (const float*)d_in[5];
    const float* bhh  = (const float*)d_in[6];
    const float* Wfc  = (const float*)d_in[7];
    const float* bfc  = (const float*)d_in[8];
    float* out = (float*)d_out;

    cudaFuncSetAttribute(ip_gemm, cudaFuncAttributeMaxDynamicSharedMemorySize, SMEMSZ_128);
    cudaFuncSetAttribute(fc_gemm, cudaFuncAttributeMaxDynamicSharedMemorySize, SMEMSZ_128);
    cudaFuncSetAttribute(lstm_mma_step, cudaFuncAttributeMaxDynamicSharedMemorySize, SMEMSZ_32);

    void* p;
    cudaGetSymbolAddress(&p, g_xf);    __half* xf   = (__half*)p;
    cudaGetSymbolAddress(&p, g_wihf);  __half* wihf = (__half*)p;
    cudaGetSymbolAddress(&p, g_wfcf);  __half* wfcf = (__half*)p;
    cudaGetSymbolAddress(&p, g_hf16);  __half* hf16 = (__half*)p;
    cudaGetSymbolAddress(&p, g_gpre);  float*  gpre = (float*)p;

    gather_f16<<<MALL, 128>>>(enc, caps, emb);
    cvt_plain_f16<<<1024, 256>>>(Wih, wihf, G4 * EMB / 4);
    cvt_whh_f16<<<2048, 256>>>(Whh);
    cvt_wfc_f16<<<2048, 256>>>(Wfc);

    // input projection: G_pre = X @ W_ih^T + b_ih + b_hh   [3072, 4096]
    ip_gemm<<<dim3(G4 / 128, MALL / 128), 256, SMEMSZ_128>>>(
        xf, wihf, bih, bhh, gpre, EMB, G4);

    for (int t = 0; t < SEQT; t++)
        lstm_mma_step<<<128, 256, SMEMSZ_32>>>(t);

    // FC: logits[b,t,:] = h @ W_fc^T + b_fc   (N padded to 12032, guarded)
    fc_gemm<<<dim3(VOCP / 128, MALL / 128), 256, SMEMSZ_128>>>(
        hf16, wfcf, bfc, out, HID, VOC);
}

// round 13
// speedup vs baseline: 2.5884x; 1.1127x over previous
#include <cuda_runtime.h>
#include <cuda_bf16.h>
#include <cuda_fp16.h>
#include <math.h>
#include <stdint.h>

constexpr int BATCH = 128, SEQT = 24, EMB = 512, HID = 1024, VOC = 12000;
constexpr int MALL = SEQT * BATCH;     // 3072, row m = t*128 + b
constexpr int G4 = 4 * HID;            // 4096
constexpr int VOCP = 12032;            // VOC padded to 128
constexpr int BK = 32;                 // K chunk
constexpr int LDT = 40;                // padded smem row stride (16-bit elems)
constexpr int STAGES = 3;
constexpr uint32_t SMEMSZ_128 = STAGES * (128 + 128) * LDT * 2;  // 61440 B
constexpr uint32_t SMEMSZ_REC = STAGES * (64 + 32) * LDT * 2;    // 23040 B

// ---------------- device scratch (allocation forbidden) ---------------------
__device__ __half g_xf[(size_t)MALL * EMB];
__device__ __half g_wihf[(size_t)G4 * EMB];
__device__ __half g_whhf[(size_t)G4 * HID];   // gate-interleaved rows
__device__ __half g_wfcf[(size_t)VOCP * HID];
__device__ __half g_hf16[(size_t)MALL * HID];
__device__ float g_gpre[(size_t)MALL * G4];
__device__ float g_cbuf[2 * BATCH * HID];

// ---------------- helpers ----------------------------------------------------
__device__ __forceinline__ uint32_t smem_u32(const void* p) {
    uint32_t a;
    asm("{ .reg .u64 t; cvta.to.shared.u64 t, %1; cvt.u32.u64 %0, t; }" : "=r"(a) : "l"(p));
    return a;
}
__device__ __forceinline__ void cp16(uint32_t d, const void* s) {
    asm volatile("cp.async.cg.shared.global [%0], [%1], 16;" :: "r"(d), "l"(s));
}
__device__ __forceinline__ void cp_commit() { asm volatile("cp.async.commit_group;"); }
template <int N> __device__ __forceinline__ void cp_wait() {
    asm volatile("cp.async.wait_group %0;" :: "n"(N));
}
__device__ __forceinline__ void ldsm4(uint32_t* r, uint32_t a) {
    asm volatile("ldmatrix.sync.aligned.m8n8.x4.shared.b16 {%0,%1,%2,%3}, [%4];"
                 : "=r"(r[0]), "=r"(r[1]), "=r"(r[2]), "=r"(r[3]) : "r"(a));
}
__device__ __forceinline__ void mma16816h(float* d, const uint32_t* a, const uint32_t* b) {
    asm volatile("mma.sync.aligned.m16n8k16.row.col.f32.f16.f16.f32 "
                 "{%0,%1,%2,%3}, {%4,%5,%6,%7}, {%8,%9}, {%0,%1,%2,%3};"
                 : "+f"(d[0]), "+f"(d[1]), "+f"(d[2]), "+f"(d[3])
                 : "r"(a[0]), "r"(a[1]), "r"(a[2]), "r"(a[3]), "r"(b[0]), "r"(b[1]));
}
__device__ __forceinline__ uint2 f16x4(float4 v) {
    __half2 a = __floats2half2_rn(v.x, v.y);
    __half2 b = __floats2half2_rn(v.z, v.w);
    return make_uint2(*reinterpret_cast<uint32_t*>(&a), *reinterpret_cast<uint32_t*>(&b));
}

// ---------------- preprocessing ----------------------------------------------
// One merged convert kernel: Wih plain | Whh interleave | Wfc padded.
// Whh interleave: dst row d -> nblk=d>>5, gate=(d>>3)&3, j=d&7 ;
// src row = gate*HID + nblk*8 + j
constexpr int S1 = G4 * EMB / 4;       // 524288
constexpr int S2 = G4 * HID / 4;       // 1048576
constexpr int S3 = VOCP * HID / 4;     // 3080192
__global__ void cvt_all(const float* __restrict__ Wih, const float* __restrict__ Whh,
                        const float* __restrict__ Wfc) {
    constexpr int TOTAL = S1 + S2 + S3;
    for (int i = blockIdx.x * blockDim.x + threadIdx.x; i < TOTAL;
         i += gridDim.x * blockDim.x) {
        if (i < S1) {
            reinterpret_cast<uint2*>(g_wihf)[i] =
                f16x4(reinterpret_cast<const float4*>(Wih)[i]);
        } else if (i < S1 + S2) {
            const int j = i - S1;
            const int d = j >> 8, k4 = j & 255;
            const int src = ((d >> 3) & 3) * HID + (d >> 5) * 8 + (d & 7);
            reinterpret_cast<uint2*>(g_whhf)[j] =
                f16x4(*reinterpret_cast<const float4*>(Whh + (size_t)src * HID + k4 * 4));
        } else {
            const int j = i - S1 - S2;
            const int r = j >> 8;
            float4 v = (r < VOC) ? reinterpret_cast<const float4*>(Wfc)[j]
                                 : make_float4(0.f, 0.f, 0.f, 0.f);
            reinterpret_cast<uint2*>(g_wfcf)[j] = f16x4(v);
        }
    }
}
__global__ void gather_f16(const float* __restrict__ enc, const int* __restrict__ caps,
                           const float* __restrict__ emb) {
    const int m = blockIdx.x, t = m >> 7, b = m & 127;
    const float* src = (t == 0) ? enc + (size_t)b * EMB
                                : emb + (size_t)caps[b * SEQT + (t - 1)] * EMB;
    const float4 v = reinterpret_cast<const float4*>(src)[threadIdx.x];
    reinterpret_cast<uint2*>(g_xf)[m * (EMB / 4) + threadIdx.x] = f16x4(v);
}

// ---------------- fp16 single-term mainloop ----------------------------------
// acc += A[MTxK] @ B[NTxK]^T. 256 threads, 8 warps.
// MT=128,NT=128: 2Mx4N (wt 64x32, MI=4,NI=4).
// MT=64, NT=32 : 4Mx2N (wt 16x16, MI=1,NI=2).
template <int MT, int NT, int MI, int NI>
__device__ __forceinline__ void gemm_main_h(
    const __half* __restrict__ A, const __half* __restrict__ B,
    int m0, int n0, int K, uint32_t sm, float (&acc)[MI][NI][4]) {
    constexpr int TAe = MT * LDT;
    constexpr int TBe = NT * LDT;
    constexpr int STAGE = TAe + TBe;
    constexpr int TOT = (MT + NT) * 4;

    const int tid = threadIdx.x, warp = tid >> 5, lane = tid & 31;
    const int wm = (MT == 128) ? (warp & 1) * 64 : (warp & 3) * 16;
    const int wn = (MT == 128) ? (warp >> 1) * 32 : (warp >> 2) * 16;
    const int l8 = lane & 7, lt = lane >> 3;
    const int nk = K / BK;

    auto load_stage = [&](int stage, int k0) {
        const uint32_t sbase = sm + stage * STAGE * 2;
#pragma unroll
        for (int idx = tid; idx < TOT; idx += 256) {
            uint32_t dst;
            const __half* src;
            if (idx < MT * 4) {
                const int r = idx >> 2, c = idx & 3;
                dst = sbase + (r * LDT + c * 8) * 2;
                src = A + (size_t)(m0 + r) * K + k0 + c * 8;
            } else {
                const int j = idx - MT * 4, r = j >> 2, c = j & 3;
                dst = sbase + (TAe + r * LDT + c * 8) * 2;
                src = B + (size_t)(n0 + r) * K + k0 + c * 8;
            }
            cp16(dst, src);
        }
        cp_commit();
    };

    load_stage(0, 0);
    load_stage(1, BK);

    for (int kc = 0; kc < nk; kc++) {
        if (kc == nk - 1) cp_wait<0>(); else cp_wait<1>();
        __syncthreads();
        if (kc + STAGES - 1 < nk)
            load_stage((kc + STAGES - 1) % STAGES, (kc + STAGES - 1) * BK);
        const uint32_t sb = sm + (kc % STAGES) * STAGE * 2;
#pragma unroll
        for (int h = 0; h < 2; h++) {
            const int kk = h * 16;
            uint32_t af[MI][4], bf[NI][2];
#pragma unroll
            for (int mi = 0; mi < MI; mi++) {
                const uint32_t ra = sb +
                    ((wm + mi * 16 + l8 + (lt & 1) * 8) * LDT + kk + (lt >> 1) * 8) * 2;
                ldsm4(af[mi], ra);
            }
#pragma unroll
            for (int nj = 0; nj < NI / 2; nj++) {
                const uint32_t rb = sb + TAe * 2 +
                    ((wn + nj * 16 + l8 + (lt >> 1) * 8) * LDT + kk + (lt & 1) * 8) * 2;
                uint32_t t4[4];
                ldsm4(t4, rb);
                bf[nj * 2][0] = t4[0]; bf[nj * 2][1] = t4[1];
                bf[nj * 2 + 1][0] = t4[2]; bf[nj * 2 + 1][1] = t4[3];
            }
#pragma unroll
            for (int mi = 0; mi < MI; mi++)
#pragma unroll
                for (int ni = 0; ni < NI; ni++)
                    mma16816h(acc[mi][ni], af[mi], bf[ni]);
        }
    }
    __syncthreads();
}

// ---------------- input-proj GEMM: C = X @ Wih^T + b_ih + b_hh ---------------
__global__ __launch_bounds__(256, 2)
void ip_gemm(const __half* __restrict__ A, const __half* __restrict__ B,
             const float* __restrict__ b1, const float* __restrict__ b2,
             float* __restrict__ C, int K, int N) {
    extern __shared__ char smraw[];
    float acc[4][4][4];
#pragma unroll
    for (int a = 0; a < 4; a++)
#pragma unroll
        for (int b = 0; b < 4; b++)
#pragma unroll
            for (int c = 0; c < 4; c++) acc[a][b][c] = 0.f;

    const int m0 = blockIdx.y * 128, n0 = blockIdx.x * 128;
    gemm_main_h<128, 128, 4, 4>(A, B, m0, n0, K, smem_u32(smraw), acc);

    const int lane = threadIdx.x & 31, warp = threadIdx.x >> 5;
    const int wm = (warp & 1) * 64, wn = (warp >> 1) * 32;
    const int g = lane >> 2, tg = lane & 3;
#pragma unroll
    for (int mi = 0; mi < 4; mi++)
#pragma unroll
        for (int half = 0; half < 2; half++) {
            const int m = m0 + wm + mi * 16 + g + half * 8;
            const size_t rowBase = (size_t)m * N;
#pragma unroll
            for (int ni = 0; ni < 4; ni++) {
                const int n = n0 + wn + ni * 8 + tg * 2;
                const float2 bb = *reinterpret_cast<const float2*>(b1 + n);
                const float2 b2v = *reinterpret_cast<const float2*>(b2 + n);
                float2 v;
                v.x = acc[mi][ni][half * 2 + 0] + bb.x + b2v.x;
                v.y = acc[mi][ni][half * 2 + 1] + bb.y + b2v.y;
                *reinterpret_cast<float2*>(C + rowBase + n) = v;
            }
        }
}

// ---------------- FC GEMM: logits reorder + bias -----------------------------
// C[(b*24+t), n] = sum_k h[m,k] * Wfc[n,k] + b_fc[n], m = t*128+b
__global__ __launch_bounds__(256, 2)
void fc_gemm(const __half* __restrict__ A, const __half* __restrict__ B,
             const float* __restrict__ b1, float* __restrict__ C, int K, int N) {
    extern __shared__ char smraw[];
    float acc[4][4][4];
#pragma unroll
    for (int a = 0; a < 4; a++)
#pragma unroll
        for (int b = 0; b < 4; b++)
#pragma unroll
            for (int c = 0; c < 4; c++) acc[a][b][c] = 0.f;

    const int m0 = blockIdx.y * 128, n0 = blockIdx.x * 128;
    gemm_main_h<128, 128, 4, 4>(A, B, m0, n0, K, smem_u32(smraw), acc);

    const int lane = threadIdx.x & 31, warp = threadIdx.x >> 5;
    const int wm = (warp & 1) * 64, wn = (warp >> 1) * 32;
    const int g = lane >> 2, tg = lane & 3;
#pragma unroll
    for (int mi = 0; mi < 4; mi++)
#pragma unroll
        for (int half = 0; half < 2; half++) {
            const int m = m0 + wm + mi * 16 + g + half * 8;
            const size_t rowBase = ((size_t)(m & 127) * SEQT + (size_t)(m >> 7)) * N;
#pragma unroll
            for (int ni = 0; ni < 4; ni++) {
                const int n = n0 + wn + ni * 8 + tg * 2;
                if (n >= N) continue;
                const float2 bb = *reinterpret_cast<const float2*>(b1 + n);
                float2 v;
                v.x = acc[mi][ni][half * 2 + 0] + bb.x;
                v.y = acc[mi][ni][half * 2 + 1] + bb.y;
                *reinterpret_cast<float2*>(C + rowBase + n) = v;
            }
        }
}

// ---------------- recurrent step: 256 CTAs, tile [64 x 32], fused cell -------
// CTA: nblk = blockIdx>>1 owns hidden [nblk*8, nblk*8+8) x 4 gates (D col
// c = gate*8 + j); mh = blockIdx&1 owns batch rows [mh*64, mh*64+64).
__global__ __launch_bounds__(256, 2)
void lstm_mma_step(int t) {
    extern __shared__ char smraw[];
    const int tid = threadIdx.x;
    const int nblk = blockIdx.x >> 1;
    const int mh = blockIdx.x & 1;
    float* Cs = reinterpret_cast<float*>(smraw);   // [64][36], reuses GEMM smem

    if (t > 0) {
        float acc[1][2][4] = {};
        gemm_main_h<64, 32, 1, 2>(
            g_hf16 + (size_t)(t - 1) * BATCH * HID + (size_t)mh * 64 * HID,
            g_whhf, 0, nblk * 32, HID, smem_u32(smraw), acc);
        const int lane = tid & 31, warp = tid >> 5;
        const int wm = (warp & 3) * 16, wn = (warp >> 2) * 16;
        const int g = lane >> 2, tg = lane & 3;
#pragma unroll
        for (int half = 0; half < 2; half++) {
            const int r = wm + g + half * 8;
#pragma unroll
            for (int ni = 0; ni < 2; ni++) {
                const int c = wn + ni * 8 + tg * 2;
                float2 v;
                v.x = acc[0][ni][half * 2 + 0];
                v.y = acc[0][ni][half * 2 + 1];
                *reinterpret_cast<float2*>(&Cs[r * 36 + c]) = v;
            }
        }
        __syncthreads();
    }

    // cell update: 4 threads per batch row, 2 hidden units each
    const int bl = tid >> 2;              // local row 0..63
    const int b = mh * 64 + bl;
    const int u0 = (tid & 3) * 2;         // unit offset 0,2,4,6
    const int j0 = nblk * 8;
    const float* gp   = g_gpre + ((size_t)t * BATCH + b) * G4;
    const float* cold = g_cbuf + (size_t)(t & 1) * BATCH * HID + (size_t)b * HID;
    float*       cnew = g_cbuf + (size_t)((t + 1) & 1) * BATCH * HID + (size_t)b * HID;
    __half*      hf   = g_hf16 + ((size_t)t * BATCH + b) * HID;

    const float2 pi = *reinterpret_cast<const float2*>(gp + 0 * HID + j0 + u0);
    const float2 pf = *reinterpret_cast<const float2*>(gp + 1 * HID + j0 + u0);
    const float2 pg = *reinterpret_cast<const float2*>(gp + 2 * HID + j0 + u0);
    const float2 po = *reinterpret_cast<const float2*>(gp + 3 * HID + j0 + u0);
    float2 co = make_float2(0.f, 0.f);
    if (t > 0) co = *reinterpret_cast<const float2*>(cold + j0 + u0);

    float cn[2], hn[2];
#pragma unroll
    for (int q = 0; q < 2; q++) {
        float ai = 0.f, af = 0.f, ag = 0.f, ao = 0.f;
        if (t > 0) {
            ai = Cs[bl * 36 + 0  + u0 + q];
            af = Cs[bl * 36 + 8  + u0 + q];
            ag = Cs[bl * 36 + 16 + u0 + q];
            ao = Cs[bl * 36 + 24 + u0 + q];
        }
        const float* pip = &pi.x; const float* pfp = &pf.x;
        const float* pgp = &pg.x; const float* pop = &po.x;
        const float* cop = &co.x;
        const float gi = 1.f / (1.f + expf(-(ai + pip[q])));
        const float gf = 1.f / (1.f + expf(-(af + pfp[q])));
        const float gg = tanhf(ag + pgp[q]);
        const float go = 1.f / (1.f + expf(-(ao + pop[q])));
        const float cv = gf * cop[q] + gi * gg;
        cn[q] = cv;
        hn[q] = go * tanhf(cv);
    }
    *reinterpret_cast<float2*>(cnew + j0 + u0) = make_float2(cn[0], cn[1]);
    __half2 hp = __floats2half2_rn(hn[0], hn[1]);
    *reinterpret_cast<uint32_t*>(hf + j0 + u0) = *reinterpret_cast<uint32_t*>(&hp);
}

// ---------------- launch ------------------------------------------------------
extern "C" void kernel_launch(void* const* d_in, const int* in_sizes, int n_in,
                              void* d_out, int out_size) {
    const float* enc  = (const float*)d_in[0];
    const int*   caps = (const int*  )d_in[1];
    const float* emb  = (const float*)d_in[2];
    const float* Wih  = (const float*)d_in[3];
    const float* Whh  = (const float*)d_in[4];
    const float* bih  = (const float*)d_in[5];
    const float* bhh  = (const float*)d_in[6];
    const float* Wfc  = (const float*)d_in[7];
    const float* bfc  = (const float*)d_in[8];
    float* out = (float*)d_out;

    cudaFuncSetAttribute(ip_gemm, cudaFuncAttributeMaxDynamicSharedMemorySize, SMEMSZ_128);
    cudaFuncSetAttribute(fc_gemm, cudaFuncAttributeMaxDynamicSharedMemorySize, SMEMSZ_128);
    cudaFuncSetAttribute(lstm_mma_step, cudaFuncAttributeMaxDynamicSharedMemorySize, SMEMSZ_REC);

    void* p;
    cudaGetSymbolAddress(&p, g_xf);    __half* xf   = (__half*)p;
    cudaGetSymbolAddress(&p, g_wihf);  __half* wihf = (__half*)p;
    cudaGetSymbolAddress(&p, g_wfcf);  __half* wfcf = (__half*)p;
    cudaGetSymbolAddress(&p, g_hf16);  __half* hf16 = (__half*)p;
    cudaGetSymbolAddress(&p, g_gpre);  float*  gpre = (float*)p;

    gather_f16<<<MALL, 128>>>(enc, caps, emb);
    cvt_all<<<4096, 256>>>(Wih, Whh, Wfc);

    // input projection: G_pre = X @ W_ih^T + b_ih + b_hh   [3072, 4096]
    ip_gemm<<<dim3(G4 / 128, MALL / 128), 256, SMEMSZ_128>>>(
        xf, wihf, bih, bhh, gpre, EMB, G4);

    for (int t = 0; t < SEQT; t++)
        lstm_mma_step<<<256, 256, SMEMSZ_REC>>>(t);

    // FC: logits[b,t,:] = h @ W_fc^T + b_fc   (N padded to 12032, guarded)
    fc_gemm<<<dim3(VOCP / 128, MALL / 128), 256, SMEMSZ_128>>>(
        hf16, wfcf, bfc, out, HID, VOC);
}